// round 15
// baseline (speedup 1.0000x reference)
#include <cuda_runtime.h>
#include <cuda_fp16.h>
#include <cstdint>

#define NNODES_MAX 100000
#define EDGES_MAX  1600000
#define DH 128
#define NGRAPH 512

// ---------------- scratch (static device globals; no allocation) ------------
__device__ __half g_x16[NNODES_MAX * DH];    // input features, fp16
__device__ __half g_h16[NNODES_MAX * DH];    // layer output h, fp16
__device__ __half g_agg16[NNODES_MAX * DH];  // h + A*h, fp16
__device__ __half g_w16[3 * DH * DH];        // W0,W1,W2 in fp16
__device__ float  g_pool[NGRAPH * DH];       // per-graph sums (zeroed by final)
__device__ float  g_cnt[NGRAPH];             // per-graph counts (zeroed by final)
__device__ int    g_deg[NNODES_MAX];         // zeroed by scan after use
__device__ int    g_cur[NNODES_MAX];
__device__ int    g_rowptr[NNODES_MAX + 1];
__device__ int    g_col[EDGES_MAX];

// ---------------- helpers ---------------------------------------------------
__device__ __forceinline__ void red2(float* p, float a, float b) {
    asm volatile("red.global.add.v2.f32 [%0], {%1,%2};"
                 :: "l"(p), "f"(a), "f"(b) : "memory");
}
// 8B feature load with 256B L2 promotion + non-coherent path
__device__ __forceinline__ uint2 ldg_nc256(const uint2* p) {
    uint2 v;
    asm volatile("ld.global.nc.L2::256B.v2.b32 {%0,%1}, [%2];"
                 : "=r"(v.x), "=r"(v.y) : "l"(p));
    return v;
}
__device__ __forceinline__ float4 h4_to_f4(uint2 u) {
    float2 fa = __half22float2(*reinterpret_cast<__half2*>(&u.x));
    float2 fb = __half22float2(*reinterpret_cast<__half2*>(&u.y));
    return make_float4(fa.x, fa.y, fb.x, fb.y);
}

// ---------------- fused preamble: hist + graph-count + x convert -------------
// g_deg/g_cnt are zero on entry (BSS at load; restored by scan/final each run)
__global__ void hist_convert_kernel(const int* __restrict__ ei,
                                    const int* __restrict__ batch,
                                    const float4* __restrict__ x,
                                    int E, int N, int n4) {
    int i = blockIdx.x * blockDim.x + threadIdx.x;
    if (i < E) atomicAdd(&g_deg[ei[E + i]], 1);   // dst degree
    if (i < N) atomicAdd(&g_cnt[batch[i]], 1.0f);
    if (i < n4) {
        float4 v = x[i];
        __half2* dst = reinterpret_cast<__half2*>(g_x16);
        dst[i * 2]     = __floats2half2_rn(v.x, v.y);
        dst[i * 2 + 1] = __floats2half2_rn(v.z, v.w);
    }
}

// single-block exclusive scan of g_deg into g_rowptr; seeds g_cur; re-zeros deg
__global__ void scan_kernel(int n) {
    const int T = 1024;
    __shared__ int part[T];
    int t = threadIdx.x;
    int C = (n + T - 1) / T;
    int beg = t * C;
    int end = beg + C < n ? beg + C : n;
    int s = 0;
    for (int i = beg; i < end; i++) s += g_deg[i];
    part[t] = s;
    __syncthreads();
    for (int off = 1; off < T; off <<= 1) {
        int v = (t >= off) ? part[t - off] : 0;
        __syncthreads();
        part[t] += v;
        __syncthreads();
    }
    int run = (t == 0) ? 0 : part[t - 1];
    for (int i = beg; i < end; i++) {
        g_rowptr[i] = run;
        g_cur[i]    = run;
        run += g_deg[i];
        g_deg[i] = 0;                 // restore for next launch
    }
    if (t == 0) g_rowptr[n] = part[T - 1];
}

__global__ void fill_kernel(const int* __restrict__ ei, int E) {
    int i = blockIdx.x * blockDim.x + threadIdx.x;
    if (i >= E) return;
    int s = ei[i];
    int d = ei[E + i];
    int pos = atomicAdd(&g_cur[d], 1);
    g_col[pos] = s;
}

// convert all three W matrices in one launch
__global__ void convert_w3_kernel(const float4* __restrict__ w0,
                                  const float4* __restrict__ w1,
                                  const float4* __restrict__ w2) {
    int i = blockIdx.x * blockDim.x + threadIdx.x;     // 0..12287
    const int n4 = DH * DH / 4;                        // 4096 per layer
    if (i >= 3 * n4) return;
    int layer = i / n4;
    int j = i - layer * n4;
    const float4* w = (layer == 0) ? w0 : (layer == 1) ? w1 : w2;
    float4 v = w[j];
    __half2* dst = reinterpret_cast<__half2*>(&g_w16[layer * DH * DH]);
    dst[j * 2]     = __floats2half2_rn(v.x, v.y);
    dst[j * 2 + 1] = __floats2half2_rn(v.z, v.w);
}

// ---------------- gather (R7-proven loop + nc/L2::256B hints) ----------------
// one warp per node; lane handles 4 halfs (uint2, 8B); serial shfl loop
__global__ void gather16_kernel(const __half* __restrict__ srcp, int N) {
    int w    = (blockIdx.x * blockDim.x + threadIdx.x) >> 5;
    int lane = threadIdx.x & 31;
    if (w >= N) return;
    const uint2* __restrict__ src = reinterpret_cast<const uint2*>(srcp);
    const int beg = g_rowptr[w];
    const int end = g_rowptr[w + 1];

    float4 acc = h4_to_f4(ldg_nc256(&src[w * 32 + lane]));   // seed: own feats
    for (int base = beg; base < end; base += 32) {
        int idx = (base + lane < end) ? g_col[base + lane] : 0;
        int cnt = end - base; if (cnt > 32) cnt = 32;
#pragma unroll 4
        for (int j = 0; j < cnt; j++) {
            int s = __shfl_sync(0xffffffffu, idx, j);
            float4 v = h4_to_f4(ldg_nc256(&src[s * 32 + lane]));
            acc.x += v.x; acc.y += v.y; acc.z += v.z; acc.w += v.w;
        }
    }
    uint2 o;
    *reinterpret_cast<__half2*>(&o.x) = __floats2half2_rn(acc.x, acc.y);
    *reinterpret_cast<__half2*>(&o.y) = __floats2half2_rn(acc.z, acc.w);
    reinterpret_cast<uint2*>(g_agg16)[w * 32 + lane] = o;
}

// ---------------- tensor-core GEMM (exact R7 form, 479us-validated) ----------
// mma.sync m16n8k16 f16*f16+f32. BM=128, BN=128, BK=64 (2 stages), 8 warps.
template<bool RELU, bool POOL>
__global__ __launch_bounds__(256)
void hgemm_kernel(const __half* __restrict__ Wh, const float* __restrict__ bias,
                  const int* __restrict__ batch, int M) {
    __shared__ __half As[128 * 72];   // [m][k], stride 72 (pad 8)
    __shared__ __half Ws[128 * 72];   // [n][k]

    const int tid  = threadIdx.x;
    const int wid  = tid >> 5;
    const int lane = tid & 31;
    const int g    = lane >> 2;       // 0..7
    const int c    = (lane & 3) * 2;  // 0,2,4,6
    const int mrow = (wid & 1) * 64;
    const int ncol = (wid >> 1) * 32;
    const int rowBase = blockIdx.x * 128;

    float acc[4][4][4];
#pragma unroll
    for (int mt = 0; mt < 4; mt++)
#pragma unroll
        for (int nt = 0; nt < 4; nt++)
#pragma unroll
            for (int q = 0; q < 4; q++) acc[mt][nt][q] = 0.f;

#pragma unroll
    for (int kc = 0; kc < DH; kc += 64) {
        __syncthreads();
        // stage A[128][64] and W[128][64] (8 halfs = uint4 per thread-chunk)
#pragma unroll
        for (int t = 0; t < 4; t++) {
            int idx = tid + t * 256;
            int row = idx >> 3;
            int ch  = (idx & 7) * 8;
            int grow = rowBase + row;
            if (grow >= M) grow = M - 1;
            *reinterpret_cast<uint4*>(&As[row * 72 + ch]) =
                *reinterpret_cast<const uint4*>(&g_agg16[grow * DH + kc + ch]);
            *reinterpret_cast<uint4*>(&Ws[row * 72 + ch]) =
                *reinterpret_cast<const uint4*>(&Wh[row * DH + kc + ch]);
        }
        __syncthreads();

#pragma unroll
        for (int kk = 0; kk < 4; kk++) {
            const int k0 = kk * 16;
            uint32_t af[4][4], bf[4][2];
#pragma unroll
            for (int mt = 0; mt < 4; mt++) {
                int rb = (mrow + mt * 16 + g) * 72 + k0 + c;
                af[mt][0] = *reinterpret_cast<const uint32_t*>(&As[rb]);
                af[mt][1] = *reinterpret_cast<const uint32_t*>(&As[rb + 8 * 72]);
                af[mt][2] = *reinterpret_cast<const uint32_t*>(&As[rb + 8]);
                af[mt][3] = *reinterpret_cast<const uint32_t*>(&As[rb + 8 * 72 + 8]);
            }
#pragma unroll
            for (int nt = 0; nt < 4; nt++) {
                int cb = (ncol + nt * 8 + g) * 72 + k0 + c;
                bf[nt][0] = *reinterpret_cast<const uint32_t*>(&Ws[cb]);
                bf[nt][1] = *reinterpret_cast<const uint32_t*>(&Ws[cb + 8]);
            }
#pragma unroll
            for (int mt = 0; mt < 4; mt++)
#pragma unroll
                for (int nt = 0; nt < 4; nt++) {
                    asm volatile(
                        "mma.sync.aligned.m16n8k16.row.col.f32.f16.f16.f32 "
                        "{%0,%1,%2,%3}, {%4,%5,%6,%7}, {%8,%9}, {%0,%1,%2,%3};"
                        : "+f"(acc[mt][nt][0]), "+f"(acc[mt][nt][1]),
                          "+f"(acc[mt][nt][2]), "+f"(acc[mt][nt][3])
                        : "r"(af[mt][0]), "r"(af[mt][1]), "r"(af[mt][2]), "r"(af[mt][3]),
                          "r"(bf[nt][0]), "r"(bf[nt][1]));
                }
        }
    }

    // epilogue
#pragma unroll
    for (int nt = 0; nt < 4; nt++) {
        int col = ncol + nt * 8 + c;
        float2 bb = *reinterpret_cast<const float2*>(&bias[col]);
#pragma unroll
        for (int mt = 0; mt < 4; mt++) {
            int row0 = rowBase + mrow + mt * 16 + g;
            int row1 = row0 + 8;
            float c0 = acc[mt][nt][0] + bb.x;
            float c1 = acc[mt][nt][1] + bb.y;
            float c2 = acc[mt][nt][2] + bb.x;
            float c3 = acc[mt][nt][3] + bb.y;
            if (RELU) {
                c0 = fmaxf(c0, 0.f); c1 = fmaxf(c1, 0.f);
                c2 = fmaxf(c2, 0.f); c3 = fmaxf(c3, 0.f);
            }
            if (POOL) {
                if (row0 < M) red2(&g_pool[batch[row0] * DH + col], c0, c1);
                if (row1 < M) red2(&g_pool[batch[row1] * DH + col], c2, c3);
            } else {
                if (row0 < M)
                    *reinterpret_cast<__half2*>(&g_h16[row0 * DH + col]) =
                        __floats2half2_rn(c0, c1);
                if (row1 < M)
                    *reinterpret_cast<__half2*>(&g_h16[row1 * DH + col]) =
                        __floats2half2_rn(c2, c3);
            }
        }
    }
}

// ---------------- head; restores pool/cnt to zero for next launch ------------
__global__ void final_kernel(const float* __restrict__ Wg,
                             const float* __restrict__ bg,
                             float* __restrict__ out) {
    int g = blockIdx.x;
    int lane = threadIdx.x;
    float4 p = reinterpret_cast<const float4*>(g_pool)[g * 32 + lane];
    float c = fmaxf(g_cnt[g], 1.0f);
#pragma unroll
    for (int o = 0; o < 10; o++) {
        float4 w = reinterpret_cast<const float4*>(Wg)[o * 32 + lane];
        float s = p.x * w.x + p.y * w.y + p.z * w.z + p.w * w.w;
#pragma unroll
        for (int off = 16; off; off >>= 1) s += __shfl_xor_sync(0xffffffffu, s, off);
        if (lane == 0) out[g * 10 + o] = s / c + bg[o];
    }
    // restore zeros (deterministic per-launch state)
    reinterpret_cast<float4*>(g_pool)[g * 32 + lane] = make_float4(0.f, 0.f, 0.f, 0.f);
    if (lane == 0) g_cnt[g] = 0.f;
}

// ---------------- launch ----------------------------------------------------
extern "C" void kernel_launch(void* const* d_in, const int* in_sizes, int n_in,
                              void* d_out, int out_size) {
    const float* x     = (const float*)d_in[0];
    const int*   ei    = (const int*)d_in[1];      // int32 (JAX x64 disabled)
    const int*   batch = (const int*)d_in[2];
    const float* W0 = (const float*)d_in[3];
    const float* b0 = (const float*)d_in[4];
    const float* W1 = (const float*)d_in[5];
    const float* b1 = (const float*)d_in[6];
    const float* W2 = (const float*)d_in[7];
    const float* b2 = (const float*)d_in[8];
    const float* Wg = (const float*)d_in[9];
    const float* bg = (const float*)d_in[10];
    float* out = (float*)d_out;

    const int N = in_sizes[0] / DH;     // 100000
    const int E = in_sizes[1] / 2;      // 1600000

    const int gemm_grid = (N + 127) / 128;
    const int gat_grid  = (N + 7) / 8;  // 8 warps/block, 1 node/warp
    const int n4 = N * (DH / 4);

    __half* w16; cudaGetSymbolAddress((void**)&w16, g_w16);
    __half* x16; cudaGetSymbolAddress((void**)&x16, g_x16);
    __half* h16; cudaGetSymbolAddress((void**)&h16, g_h16);

    // preamble (deg/cnt/pool zero on entry; restored by scan/final)
    hist_convert_kernel<<<(n4 + 511) / 512, 512>>>(          // idx 0
        ei, batch, reinterpret_cast<const float4*>(x), E, N, n4);
    scan_kernel<<<1, 1024>>>(N);                             // idx 1
    fill_kernel<<<(E + 511) / 512, 512>>>(ei, E);            // idx 2

    // layer 0 — gather at launch index 3 (ncu capture slot)
    gather16_kernel<<<gat_grid, 256>>>(x16, N);              // idx 3 (profiled)
    convert_w3_kernel<<<24, 512>>>(reinterpret_cast<const float4*>(W0),
                                   reinterpret_cast<const float4*>(W1),
                                   reinterpret_cast<const float4*>(W2));
    hgemm_kernel<true, false><<<gemm_grid, 256>>>(w16, b0, nullptr, N);
    // layer 1
    gather16_kernel<<<gat_grid, 256>>>(h16, N);
    hgemm_kernel<true, false><<<gemm_grid, 256>>>(w16 + DH * DH, b1, nullptr, N);
    // layer 2 + fused pooling
    gather16_kernel<<<gat_grid, 256>>>(h16, N);
    hgemm_kernel<false, true><<<gemm_grid, 256>>>(w16 + 2 * DH * DH, b2, batch, N);

    final_kernel<<<NGRAPH, 32>>>(Wg, bg, out);
}

// round 16
// speedup vs baseline: 1.0236x; 1.0236x over previous
#include <cuda_runtime.h>
#include <cuda_fp16.h>
#include <cstdint>

#define NNODES_MAX 100000
#define EDGES_MAX  1600000
#define DH 128
#define NGRAPH 512

// hgemm smem: Ws[128][136] + A0[128][136] + A1[128][136] halfs
#define HG_STRIDE 136
#define HG_TILE_HALFS (128 * HG_STRIDE)
#define HG_SMEM_BYTES (3 * HG_TILE_HALFS * 2)

// ---------------- scratch (static device globals; no allocation) ------------
__device__ __half g_x16[NNODES_MAX * DH];    // input features, fp16
__device__ __half g_h16[NNODES_MAX * DH];    // layer output h, fp16
__device__ __half g_agg16[NNODES_MAX * DH];  // h + A*h, fp16
__device__ __half g_w16[3 * DH * DH];        // W0,W1,W2 in fp16
__device__ float  g_pool[NGRAPH * DH];       // per-graph sums (zeroed by final)
__device__ float  g_cnt[NGRAPH];             // per-graph counts (zeroed by final)
__device__ int    g_deg[NNODES_MAX];         // zeroed by scan after use
__device__ int    g_cur[NNODES_MAX];
__device__ int    g_rowptr[NNODES_MAX + 1];
__device__ int    g_col[EDGES_MAX];

// ---------------- helpers ---------------------------------------------------
__device__ __forceinline__ void red2(float* p, float a, float b) {
    asm volatile("red.global.add.v2.f32 [%0], {%1,%2};"
                 :: "l"(p), "f"(a), "f"(b) : "memory");
}
__device__ __forceinline__ uint2 ldg_nc256(const uint2* p) {
    uint2 v;
    asm volatile("ld.global.nc.L2::256B.v2.b32 {%0,%1}, [%2];"
                 : "=r"(v.x), "=r"(v.y) : "l"(p));
    return v;
}
__device__ __forceinline__ float4 h4_to_f4(uint2 u) {
    float2 fa = __half22float2(*reinterpret_cast<__half2*>(&u.x));
    float2 fb = __half22float2(*reinterpret_cast<__half2*>(&u.y));
    return make_float4(fa.x, fa.y, fb.x, fb.y);
}
__device__ __forceinline__ void cpasync16(uint32_t daddr, const void* gaddr) {
    asm volatile("cp.async.cg.shared.global [%0], [%1], 16;"
                 :: "r"(daddr), "l"(gaddr) : "memory");
}

// ---------------- fused preamble: hist + graph-count + x convert -------------
__global__ void hist_convert_kernel(const int* __restrict__ ei,
                                    const int* __restrict__ batch,
                                    const float4* __restrict__ x,
                                    int E, int N, int n4) {
    int i = blockIdx.x * blockDim.x + threadIdx.x;
    if (i < E) atomicAdd(&g_deg[ei[E + i]], 1);   // dst degree
    if (i < N) atomicAdd(&g_cnt[batch[i]], 1.0f);
    if (i < n4) {
        float4 v = x[i];
        __half2* dst = reinterpret_cast<__half2*>(g_x16);
        dst[i * 2]     = __floats2half2_rn(v.x, v.y);
        dst[i * 2 + 1] = __floats2half2_rn(v.z, v.w);
    }
}

// single-block exclusive scan of g_deg into g_rowptr; seeds g_cur; re-zeros deg
__global__ void scan_kernel(int n) {
    const int T = 1024;
    __shared__ int part[T];
    int t = threadIdx.x;
    int C = (n + T - 1) / T;
    int beg = t * C;
    int end = beg + C < n ? beg + C : n;
    int s = 0;
    for (int i = beg; i < end; i++) s += g_deg[i];
    part[t] = s;
    __syncthreads();
    for (int off = 1; off < T; off <<= 1) {
        int v = (t >= off) ? part[t - off] : 0;
        __syncthreads();
        part[t] += v;
        __syncthreads();
    }
    int run = (t == 0) ? 0 : part[t - 1];
    for (int i = beg; i < end; i++) {
        g_rowptr[i] = run;
        g_cur[i]    = run;
        run += g_deg[i];
        g_deg[i] = 0;                 // restore for next launch
    }
    if (t == 0) g_rowptr[n] = part[T - 1];
}

__global__ void fill_kernel(const int* __restrict__ ei, int E) {
    int i = blockIdx.x * blockDim.x + threadIdx.x;
    if (i >= E) return;
    int s = ei[i];
    int d = ei[E + i];
    int pos = atomicAdd(&g_cur[d], 1);
    g_col[pos] = s;
}

__global__ void convert_w3_kernel(const float4* __restrict__ w0,
                                  const float4* __restrict__ w1,
                                  const float4* __restrict__ w2) {
    int i = blockIdx.x * blockDim.x + threadIdx.x;     // 0..12287
    const int n4 = DH * DH / 4;                        // 4096 per layer
    if (i >= 3 * n4) return;
    int layer = i / n4;
    int j = i - layer * n4;
    const float4* w = (layer == 0) ? w0 : (layer == 1) ? w1 : w2;
    float4 v = w[j];
    __half2* dst = reinterpret_cast<__half2*>(&g_w16[layer * DH * DH]);
    dst[j * 2]     = __floats2half2_rn(v.x, v.y);
    dst[j * 2 + 1] = __floats2half2_rn(v.z, v.w);
}

// ---------------- gather (R7-proven loop + nc/L2::256B hints) ----------------
__global__ void gather16_kernel(const __half* __restrict__ srcp, int N) {
    int w    = (blockIdx.x * blockDim.x + threadIdx.x) >> 5;
    int lane = threadIdx.x & 31;
    if (w >= N) return;
    const uint2* __restrict__ src = reinterpret_cast<const uint2*>(srcp);
    const int beg = g_rowptr[w];
    const int end = g_rowptr[w + 1];

    float4 acc = h4_to_f4(ldg_nc256(&src[w * 32 + lane]));   // seed: own feats
    for (int base = beg; base < end; base += 32) {
        int idx = (base + lane < end) ? g_col[base + lane] : 0;
        int cnt = end - base; if (cnt > 32) cnt = 32;
#pragma unroll 4
        for (int j = 0; j < cnt; j++) {
            int s = __shfl_sync(0xffffffffu, idx, j);
            float4 v = h4_to_f4(ldg_nc256(&src[s * 32 + lane]));
            acc.x += v.x; acc.y += v.y; acc.z += v.z; acc.w += v.w;
        }
    }
    uint2 o;
    *reinterpret_cast<__half2*>(&o.x) = __floats2half2_rn(acc.x, acc.y);
    *reinterpret_cast<__half2*>(&o.y) = __floats2half2_rn(acc.z, acc.w);
    reinterpret_cast<uint2*>(g_agg16)[w * 32 + lane] = o;
}

// ---------------- hgemm v2: W-resident, cp.async double-buffered tiles -------
// grid ~2/SM; each block loops M-tiles (stride gridDim). W staged ONCE.
// A tile t+1 prefetched (cp.async) during compute of tile t. ldmatrix frags.
template<bool RELU, bool POOL>
__global__ __launch_bounds__(256)
void hgemm_kernel(const __half* __restrict__ Wh, const float* __restrict__ bias,
                  const int* __restrict__ batch, int M, int nTiles) {
    extern __shared__ __half smem[];
    __half* Ws = smem;                              // [128][HG_STRIDE]
    __half* Ab[2] = { smem + HG_TILE_HALFS, smem + 2 * HG_TILE_HALFS };

    const int tid  = threadIdx.x;
    const int wid  = tid >> 5;
    const int lane = tid & 31;
    const int g    = lane >> 2;
    const int c    = (lane & 3) * 2;
    const int mrow = (wid & 1) * 64;
    const int ncol = (wid >> 1) * 32;

    // stage W once (2048 x 16B chunks, 8 per thread)
    const uint32_t ws_base = (uint32_t)__cvta_generic_to_shared(Ws);
#pragma unroll
    for (int t = 0; t < 8; t++) {
        int cdx = tid + t * 256;
        int row = cdx >> 4;
        int off = (cdx & 15) * 8;
        cpasync16(ws_base + (row * HG_STRIDE + off) * 2, &Wh[row * DH + off]);
    }
    // stage first A tile
    int tile = blockIdx.x;
    const uint32_t ab_base[2] = {
        (uint32_t)__cvta_generic_to_shared(Ab[0]),
        (uint32_t)__cvta_generic_to_shared(Ab[1]) };
    if (tile < nTiles) {
        int rowBase = tile * 128;
#pragma unroll
        for (int t = 0; t < 8; t++) {
            int cdx = tid + t * 256;
            int row = cdx >> 4;
            int off = (cdx & 15) * 8;
            int grow = rowBase + row;
            if (grow >= M) grow = M - 1;
            cpasync16(ab_base[0] + (row * HG_STRIDE + off) * 2,
                      &g_agg16[grow * DH + off]);
        }
    }
    asm volatile("cp.async.commit_group;" ::: "memory");

    // per-warp bias (constant across tiles)
    float2 bb[4];
#pragma unroll
    for (int nt = 0; nt < 4; nt++)
        bb[nt] = *reinterpret_cast<const float2*>(&bias[ncol + nt * 8 + c]);

    int buf = 0;
    for (; tile < nTiles; tile += gridDim.x, buf ^= 1) {
        asm volatile("cp.async.wait_group 0;" ::: "memory");
        __syncthreads();   // tile data ready; prior readers of other buf done

        // prefetch next tile into the other buffer (overlaps compute below)
        int nxt = tile + gridDim.x;
        if (nxt < nTiles) {
            int rowBase = nxt * 128;
#pragma unroll
            for (int t = 0; t < 8; t++) {
                int cdx = tid + t * 256;
                int row = cdx >> 4;
                int off = (cdx & 15) * 8;
                int grow = rowBase + row;
                if (grow >= M) grow = M - 1;
                cpasync16(ab_base[buf ^ 1] + (row * HG_STRIDE + off) * 2,
                          &g_agg16[grow * DH + off]);
            }
        }
        asm volatile("cp.async.commit_group;" ::: "memory");

        // ---- compute on Ab[buf] ----
        const __half* As = Ab[buf];
        float acc[4][4][4];
#pragma unroll
        for (int mt = 0; mt < 4; mt++)
#pragma unroll
            for (int nt = 0; nt < 4; nt++)
#pragma unroll
                for (int q = 0; q < 4; q++) acc[mt][nt][q] = 0.f;

#pragma unroll
        for (int kk = 0; kk < 8; kk++) {
            const int k0 = kk * 16;
            uint32_t af[4][4], bf[4][2];
#pragma unroll
            for (int mt = 0; mt < 4; mt++) {
                uint32_t aaddr = (uint32_t)__cvta_generic_to_shared(
                    &As[(mrow + mt * 16 + (lane & 15)) * HG_STRIDE + k0 + ((lane >> 4) << 3)]);
                asm volatile(
                    "ldmatrix.sync.aligned.m8n8.x4.shared.b16 {%0,%1,%2,%3}, [%4];"
                    : "=r"(af[mt][0]), "=r"(af[mt][1]),
                      "=r"(af[mt][2]), "=r"(af[mt][3])
                    : "r"(aaddr));
            }
#pragma unroll
            for (int nt = 0; nt < 4; nt++) {
                uint32_t baddr = (uint32_t)__cvta_generic_to_shared(
                    &Ws[(ncol + nt * 8 + (lane & 7)) * HG_STRIDE + k0 + (((lane >> 3) & 1) << 3)]);
                asm volatile(
                    "ldmatrix.sync.aligned.m8n8.x2.shared.b16 {%0,%1}, [%2];"
                    : "=r"(bf[nt][0]), "=r"(bf[nt][1])
                    : "r"(baddr));
            }
#pragma unroll
            for (int mt = 0; mt < 4; mt++)
#pragma unroll
                for (int nt = 0; nt < 4; nt++) {
                    asm volatile(
                        "mma.sync.aligned.m16n8k16.row.col.f32.f16.f16.f32 "
                        "{%0,%1,%2,%3}, {%4,%5,%6,%7}, {%8,%9}, {%0,%1,%2,%3};"
                        : "+f"(acc[mt][nt][0]), "+f"(acc[mt][nt][1]),
                          "+f"(acc[mt][nt][2]), "+f"(acc[mt][nt][3])
                        : "r"(af[mt][0]), "r"(af[mt][1]), "r"(af[mt][2]), "r"(af[mt][3]),
                          "r"(bf[nt][0]), "r"(bf[nt][1]));
                }
        }

        // ---- epilogue for this tile ----
        const int rowBase = tile * 128;
#pragma unroll
        for (int nt = 0; nt < 4; nt++) {
            int col = ncol + nt * 8 + c;
#pragma unroll
            for (int mt = 0; mt < 4; mt++) {
                int row0 = rowBase + mrow + mt * 16 + g;
                int row1 = row0 + 8;
                float c0 = acc[mt][nt][0] + bb[nt].x;
                float c1 = acc[mt][nt][1] + bb[nt].y;
                float c2 = acc[mt][nt][2] + bb[nt].x;
                float c3 = acc[mt][nt][3] + bb[nt].y;
                if (RELU) {
                    c0 = fmaxf(c0, 0.f); c1 = fmaxf(c1, 0.f);
                    c2 = fmaxf(c2, 0.f); c3 = fmaxf(c3, 0.f);
                }
                if (POOL) {
                    if (row0 < M) red2(&g_pool[batch[row0] * DH + col], c0, c1);
                    if (row1 < M) red2(&g_pool[batch[row1] * DH + col], c2, c3);
                } else {
                    if (row0 < M)
                        *reinterpret_cast<__half2*>(&g_h16[row0 * DH + col]) =
                            __floats2half2_rn(c0, c1);
                    if (row1 < M)
                        *reinterpret_cast<__half2*>(&g_h16[row1 * DH + col]) =
                            __floats2half2_rn(c2, c3);
                }
            }
        }
    }
}

// ---------------- head; restores pool/cnt to zero for next launch ------------
__global__ void final_kernel(const float* __restrict__ Wg,
                             const float* __restrict__ bg,
                             float* __restrict__ out) {
    int g = blockIdx.x;
    int lane = threadIdx.x;
    float4 p = reinterpret_cast<const float4*>(g_pool)[g * 32 + lane];
    float c = fmaxf(g_cnt[g], 1.0f);
#pragma unroll
    for (int o = 0; o < 10; o++) {
        float4 w = reinterpret_cast<const float4*>(Wg)[o * 32 + lane];
        float s = p.x * w.x + p.y * w.y + p.z * w.z + p.w * w.w;
#pragma unroll
        for (int off = 16; off; off >>= 1) s += __shfl_xor_sync(0xffffffffu, s, off);
        if (lane == 0) out[g * 10 + o] = s / c + bg[o];
    }
    reinterpret_cast<float4*>(g_pool)[g * 32 + lane] = make_float4(0.f, 0.f, 0.f, 0.f);
    if (lane == 0) g_cnt[g] = 0.f;
}

// ---------------- launch ----------------------------------------------------
extern "C" void kernel_launch(void* const* d_in, const int* in_sizes, int n_in,
                              void* d_out, int out_size) {
    const float* x     = (const float*)d_in[0];
    const int*   ei    = (const int*)d_in[1];      // int32 (JAX x64 disabled)
    const int*   batch = (const int*)d_in[2];
    const float* W0 = (const float*)d_in[3];
    const float* b0 = (const float*)d_in[4];
    const float* W1 = (const float*)d_in[5];
    const float* b1 = (const float*)d_in[6];
    const float* W2 = (const float*)d_in[7];
    const float* b2 = (const float*)d_in[8];
    const float* Wg = (const float*)d_in[9];
    const float* bg = (const float*)d_in[10];
    float* out = (float*)d_out;

    const int N = in_sizes[0] / DH;     // 100000
    const int E = in_sizes[1] / 2;      // 1600000

    const int nTiles = (N + 127) / 128;            // 782
    const int gemm_grid = nTiles < 296 ? nTiles : 296;
    const int gat_grid  = (N + 7) / 8;
    const int n4 = N * (DH / 4);

    cudaFuncSetAttribute(hgemm_kernel<true, false>,
                         cudaFuncAttributeMaxDynamicSharedMemorySize, HG_SMEM_BYTES);
    cudaFuncSetAttribute(hgemm_kernel<false, true>,
                         cudaFuncAttributeMaxDynamicSharedMemorySize, HG_SMEM_BYTES);

    __half* w16; cudaGetSymbolAddress((void**)&w16, g_w16);
    __half* x16; cudaGetSymbolAddress((void**)&x16, g_x16);
    __half* h16; cudaGetSymbolAddress((void**)&h16, g_h16);

    // preamble (deg/cnt/pool zero on entry; restored by scan/final)
    hist_convert_kernel<<<(n4 + 511) / 512, 512>>>(
        ei, batch, reinterpret_cast<const float4*>(x), E, N, n4);
    scan_kernel<<<1, 1024>>>(N);
    fill_kernel<<<(E + 511) / 512, 512>>>(ei, E);

    // layer 0 (hgemm of layer 0 sits at launch idx 5; gather stays idx 3)
    gather16_kernel<<<gat_grid, 256>>>(x16, N);
    convert_w3_kernel<<<24, 512>>>(reinterpret_cast<const float4*>(W0),
                                   reinterpret_cast<const float4*>(W1),
                                   reinterpret_cast<const float4*>(W2));
    hgemm_kernel<true, false><<<gemm_grid, 256, HG_SMEM_BYTES>>>(w16, b0, nullptr, N, nTiles);
    // layer 1
    gather16_kernel<<<gat_grid, 256>>>(h16, N);
    hgemm_kernel<true, false><<<gemm_grid, 256, HG_SMEM_BYTES>>>(w16 + DH * DH, b1, nullptr, N, nTiles);
    // layer 2 + fused pooling
    gather16_kernel<<<gat_grid, 256>>>(h16, N);
    hgemm_kernel<false, true><<<gemm_grid, 256, HG_SMEM_BYTES>>>(w16 + 2 * DH * DH, b2, batch, N, nTiles);

    final_kernel<<<NGRAPH, 32>>>(Wg, bg, out);
}